// round 12
// baseline (speedup 1.0000x reference)
#include <cuda_runtime.h>
#include <cuda_bf16.h>
#include <cstdint>
#include <math.h>

#define D 256
#define N_SEQ 2048
#define NB 16
#define NTOK (NB*N_SEQ)

// -------- persistent scratch (device globals) --------
__device__ float g_s4[NTOK*4];                        // (s0,s1,s2,|s|^2)
__device__ float g_msg[(size_t)NTOK*D];               // msg fp32 (for transpose)
__device__ float g_gi[(size_t)NTOK*3*D];
__device__ float g_gh[(size_t)NTOK*3*D];
__device__ float g_E[(size_t)NB*N_SEQ*N_SEQ];         // exp(-dist), fp32 (268MB)

// bf16 hi/lo planes
__device__ __nv_bfloat16 g_xH[(size_t)NTOK*D],   g_xL[(size_t)NTOK*D];
__device__ __nv_bfloat16 g_h1H[(size_t)NTOK*D],  g_h1L[(size_t)NTOK*D];
__device__ __nv_bfloat16 g_xinH[(size_t)NTOK*2*D], g_xinL[(size_t)NTOK*2*D];
__device__ __nv_bfloat16 g_mtH[(size_t)NB*D*N_SEQ], g_mtL[(size_t)NB*D*N_SEQ];
__device__ __nv_bfloat16 g_w1H[D*D],      g_w1L[D*D];
__device__ __nv_bfloat16 g_wmH[D*D],      g_wmL[D*D];
__device__ __nv_bfloat16 g_whhH[3*D*D],   g_whhL[3*D*D];
__device__ __nv_bfloat16 g_wihH[3*D*2*D], g_wihL[3*D*2*D];
__device__ __nv_bfloat16 g_w2H[D*D*17],   g_w2L[D*D*17];

// ======================= asm helpers =======================
__device__ __forceinline__ void cpa(uint32_t d, const void* s, int sz){
    asm volatile("cp.async.cg.shared.global [%0], [%1], 16, %2;"
                 :: "r"(d), "l"(s), "r"(sz) : "memory");
}
#define CP_COMMIT() asm volatile("cp.async.commit_group;" ::: "memory")
#define CP_WAIT1()  asm volatile("cp.async.wait_group 1;" ::: "memory")

__device__ __forceinline__ void ldsm4(uint32_t& r0,uint32_t& r1,uint32_t& r2,uint32_t& r3,uint32_t a){
    asm volatile("ldmatrix.sync.aligned.m8n8.x4.shared.b16 {%0,%1,%2,%3}, [%4];"
                 : "=r"(r0),"=r"(r1),"=r"(r2),"=r"(r3) : "r"(a));
}
__device__ __forceinline__ void mma16816(float* d, const uint32_t* a, const uint32_t* b){
    asm volatile(
        "mma.sync.aligned.m16n8k16.row.col.f32.bf16.bf16.f32 "
        "{%0,%1,%2,%3}, {%4,%5,%6,%7}, {%8,%9}, {%0,%1,%2,%3};"
        : "+f"(d[0]), "+f"(d[1]), "+f"(d[2]), "+f"(d[3])
        : "r"(a[0]), "r"(a[1]), "r"(a[2]), "r"(a[3]), "r"(b[0]), "r"(b[1]));
}
__device__ __forceinline__ void split2(float x0, float x1, uint32_t& h, uint32_t& l){
    __nv_bfloat162 hh = __floats2bfloat162_rn(x0, x1);
    float r0 = x0 - __bfloat162float(hh.x);
    float r1 = x1 - __bfloat162float(hh.y);
    __nv_bfloat162 ll = __floats2bfloat162_rn(r0, r1);
    h = *(uint32_t*)&hh; l = *(uint32_t*)&ll;
}

// mm_gemm smem: 48B row stride, 128 rows per plane => 6144 B/plane
#define PLANE 6144
#define STAGE (4*PLANE)          // AH, AL, WH, WL
#define SMEM_BYTES (3*STAGE)     // 73728
// nmp_gemm smem: A 128 rows (2 planes x 6144), B 256 rows (2 planes x 12288)
#define NSTAGE 36864
#define NSMEM_BYTES (3*NSTAGE)   // 110592

// ======================= prep kernels =======================
__global__ void split_arr(const float* __restrict__ s, __nv_bfloat16* __restrict__ H,
                          __nv_bfloat16* __restrict__ L, int n){
    int i = blockIdx.x*256 + threadIdx.x;
    if (i < n){
        float v = s[i];
        __nv_bfloat16 h = __float2bfloat16(v);
        H[i] = h; L[i] = __float2bfloat16(v - __bfloat162float(h));
    }
}
__global__ void repack_w2_split(const float* __restrict__ w){
    int idx = blockIdx.x*256 + threadIdx.x;
    if (idx < D*D*17){
        int o = idx/(D*17); int r = idx%(D*17); int k = r/D; int i = r%D;
        float v = w[(size_t)o*D*17 + (size_t)i*17 + k];
        __nv_bfloat16 h = __float2bfloat16(v);
        g_w2H[idx] = h; g_w2L[idx] = __float2bfloat16(v - __bfloat162float(h));
    }
}
__global__ void se_kernel(const float* __restrict__ x,
                          const float* __restrict__ w_se,
                          const float* __restrict__ b_se){
    int tok = blockIdx.x*8 + (threadIdx.x>>5);
    int lane = threadIdx.x & 31;
    const float* xp = x + (size_t)tok*D;
    float d0=0.f, d1=0.f, d2=0.f;
    #pragma unroll
    for (int i=lane; i<D; i+=32){
        float xv = xp[i];
        d0 += xv*w_se[i]; d1 += xv*w_se[D+i]; d2 += xv*w_se[2*D+i];
    }
    #pragma unroll
    for (int o=16;o;o>>=1){
        d0 += __shfl_down_sync(0xffffffffu,d0,o);
        d1 += __shfl_down_sync(0xffffffffu,d1,o);
        d2 += __shfl_down_sync(0xffffffffu,d2,o);
    }
    if (lane==0){
        float s0=d0+b_se[0], s1=d1+b_se[1], s2=d2+b_se[2];
        ((float4*)g_s4)[tok] = make_float4(s0,s1,s2, s0*s0+s1*s1+s2*s2);
    }
}

// E[i,j] = exp(-dist(i,j)) for tile pairs j0 >= i0, mirrored by symmetry.
// Et stride 68 floats = 272 B (multiple of 16) so float4 row writes are aligned.
__global__ __launch_bounds__(256) void exp_kernel(){
    __shared__ float4 sI[64], sJ[64];
    __shared__ float Et[64][68];
    int i0 = blockIdx.x*64, j0 = blockIdx.y*64;
    if (j0 < i0) return;
    int b = blockIdx.z;
    int tid = threadIdx.x;
    if (tid < 64)       sI[tid]    = ((const float4*)g_s4)[b*N_SEQ + i0 + tid];
    else if (tid < 128) sJ[tid-64] = ((const float4*)g_s4)[b*N_SEQ + j0 + tid-64];
    __syncthreads();
    int r0 = (tid>>4)*4;
    int c0 = (tid&15)*4;
    #pragma unroll
    for (int rr=0; rr<4; rr++){
        float4 si = sI[r0+rr];
        #pragma unroll
        for (int cc=0; cc<4; cc++){
            float4 sj = sJ[c0+cc];
            float dist = si.w + sj.w - 2.f*(si.x*sj.x + si.y*sj.y + si.z*sj.z);
            Et[r0+rr][c0+cc] = __expf(-dist);
        }
    }
    __syncthreads();
    float* Eb = g_E + (size_t)b*N_SEQ*N_SEQ;
    int wr = tid>>2;
    int wc = (tid&3)*16;
    #pragma unroll
    for (int q=0;q<4;q++){
        float4 v = *(float4*)&Et[wr][wc+4*q];
        *(float4*)(Eb + (size_t)(i0+wr)*N_SEQ + j0 + wc + 4*q) = v;
    }
    if (i0 != j0){
        #pragma unroll
        for (int q=0;q<4;q++){
            float4 v = make_float4(Et[wc+4*q+0][wr], Et[wc+4*q+1][wr],
                                   Et[wc+4*q+2][wr], Et[wc+4*q+3][wr]);
            *(float4*)(Eb + (size_t)(j0+wr)*N_SEQ + i0 + wc + 4*q) = v;
        }
    }
}

__global__ void transpose_msg(){
    __shared__ float ts[32][33];
    int b = blockIdx.z;
    int t0 = blockIdx.x*32, d0 = blockIdx.y*32;
    int tx = threadIdx.x & 31, ty = threadIdx.x >> 5;
    #pragma unroll
    for (int k=0;k<4;k++)
        ts[ty+8*k][tx] = g_msg[((size_t)(b*N_SEQ) + t0+ty+8*k)*D + d0+tx];
    __syncthreads();
    #pragma unroll
    for (int k=0;k<4;k++){
        float v = ts[tx][ty+8*k];
        size_t o = ((size_t)b*D + d0+ty+8*k)*N_SEQ + t0+tx;
        __nv_bfloat16 h = __float2bfloat16(v);
        g_mtH[o] = h; g_mtL[o] = __float2bfloat16(v - __bfloat162float(h));
    }
}
__device__ __forceinline__ float sigf(float a){ return 1.f/(1.f + __expf(-a)); }
__global__ void combine_kernel(const float* __restrict__ x, float* __restrict__ out){
    int idx = blockIdx.x*256 + threadIdx.x;
    int tok = idx >> 6;
    int c4  = (idx & 63)*4;
    const float* gi = g_gi + (size_t)tok*3*D;
    const float* gh = g_gh + (size_t)tok*3*D;
    float4 gir=*(const float4*)(gi+c4), giz=*(const float4*)(gi+D+c4), gin=*(const float4*)(gi+2*D+c4);
    float4 ghr=*(const float4*)(gh+c4), ghz=*(const float4*)(gh+D+c4), ghn=*(const float4*)(gh+2*D+c4);
    float4 xv =*(const float4*)(x + (size_t)tok*D + c4);
    float4 o;
    { float r=sigf(gir.x+ghr.x), z=sigf(giz.x+ghz.x); o.x=(1.f-z)*tanhf(gin.x+r*ghn.x)+z*xv.x; }
    { float r=sigf(gir.y+ghr.y), z=sigf(giz.y+ghz.y); o.y=(1.f-z)*tanhf(gin.y+r*ghn.y)+z*xv.y; }
    { float r=sigf(gir.z+ghr.z), z=sigf(giz.z+ghz.z); o.z=(1.f-z)*tanhf(gin.z+r*ghn.z)+z*xv.z; }
    { float r=sigf(gir.w+ghr.w), z=sigf(giz.w+ghz.w); o.w=(1.f-z)*tanhf(gin.w+r*ghn.w)+z*xv.w; }
    *(float4*)(out + (size_t)tok*D + c4) = o;
}

// ======================= bf16x3 GEMM (cp.async + ldmatrix) =======================
template<int ASRC, int MODE, bool WBATCH, bool OUTHL>
__global__ __launch_bounds__(256, 2) void mm_gemm(
    const __nv_bfloat16* __restrict__ AHp, const __nv_bfloat16* __restrict__ ALp, int lda,
    const __nv_bfloat16* __restrict__ WHp, const __nv_bfloat16* __restrict__ WLp, int ldw,
    float* __restrict__ Cf, __nv_bfloat16* __restrict__ CH, __nv_bfloat16* __restrict__ CL,
    int ldc, int coff, int K,
    const float* __restrict__ bias,
    const float* __restrict__ bng, const float* __restrict__ bnb,
    const float* __restrict__ bnm, const float* __restrict__ bnv,
    const float* __restrict__ res)
{
    extern __shared__ char sm[];
    const uint32_t smb = (uint32_t)__cvta_generic_to_shared(sm);

    const int tid  = threadIdx.x;
    const int wid  = tid >> 5;
    const int lane = tid & 31;
    const int gid  = lane >> 2;
    const int tig  = lane & 3;
    const int wm   = wid & 3;
    const int wn   = wid >> 2;

    const int b  = blockIdx.z;
    const int m0 = blockIdx.y * 128;
    const int n0 = blockIdx.x * 128;

    const __nv_bfloat16* AHb = (ASRC==1) ? AHp : AHp + (size_t)b*N_SEQ*lda;
    const __nv_bfloat16* ALb = (ASRC==1) ? ALp : ALp + (size_t)b*N_SEQ*lda;
    const __nv_bfloat16* AH1 = AHp + (size_t)b*N_SEQ*256;
    const __nv_bfloat16* AL1 = ALp + (size_t)b*N_SEQ*256;
    const __nv_bfloat16* WHb = WHp + (WBATCH ? (size_t)b*256*(size_t)ldw : 0);
    const __nv_bfloat16* WLb = WLp + (WBATCH ? (size_t)b*256*(size_t)ldw : 0);

    const int row  = tid >> 1;
    const int half = tid & 1;
    const int nchunk = K / 16;

    float acc[2][8][4];
    #pragma unroll
    for (int mt=0;mt<2;mt++)
        #pragma unroll
        for (int nt=0;nt<8;nt++)
            #pragma unroll
            for (int e=0;e<4;e++) acc[mt][nt][e]=0.f;

    const uint32_t dAH = row*48 + half*16;
    const uint32_t dAL = PLANE   + dAH;
    const uint32_t dWH = 2*PLANE + dAH;
    const uint32_t dWL = 3*PLANE + dAH;

    auto issue = [&](int c){
        const uint32_t sb = smb + (c%3)*STAGE;
        const int kt = c*16;
        const int kk = kt + half*8;
        if (ASRC == 0){
            const size_t ao = (size_t)(m0+row)*lda + kk;
            cpa(sb + dAH, AHb + ao, 16);
            cpa(sb + dAL, ALb + ao, 16);
        } else {
            const int tap = kk >> 8;
            const int ch  = kk & 255;
            int srct = m0 + row + tap - 8;
            const int ok = (srct >= 0 && srct < N_SEQ) ? 16 : 0;
            srct = srct < 0 ? 0 : (srct >= N_SEQ ? N_SEQ-1 : srct);
            const size_t ao = (size_t)srct*256 + ch;
            cpa(sb + dAH, AH1 + ao, ok);
            cpa(sb + dAL, AL1 + ao, ok);
        }
        const size_t wo = (size_t)(n0+row)*ldw + kk;
        cpa(sb + dWH, WHb + wo, 16);
        cpa(sb + dWL, WLb + wo, 16);
    };

    const uint32_t arow = (lane & 7) + (lane & 8);
    const uint32_t aoff = ((lane >> 4) & 1) * 16;
    const uint32_t brow = (lane & 7) + ((lane & 16) ? 8 : 0);
    const uint32_t boff = ((lane >> 3) & 1) * 16;
    uint32_t aAddr[2], bAddr[4];
    #pragma unroll
    for (int mt=0;mt<2;mt++)
        aAddr[mt] = (wm*32 + mt*16 + arow)*48 + aoff;
    #pragma unroll
    for (int ntp=0;ntp<4;ntp++)
        bAddr[ntp] = (wn*64 + ntp*16 + brow)*48 + boff;

    issue(0); CP_COMMIT();
    issue(1); CP_COMMIT();

    for (int c = 0; c < nchunk; c++){
        CP_WAIT1();
        __syncthreads();
        const uint32_t sb = smb + (c%3)*STAGE;

        uint32_t afH[2][4], afL[2][4];
        #pragma unroll
        for (int mt=0;mt<2;mt++){
            ldsm4(afH[mt][0],afH[mt][1],afH[mt][2],afH[mt][3], sb + aAddr[mt]);
            ldsm4(afL[mt][0],afL[mt][1],afL[mt][2],afL[mt][3], sb + PLANE + aAddr[mt]);
        }
        #pragma unroll
        for (int ntp=0;ntp<4;ntp++){
            uint32_t h0,h1,h2,h3, l0,l1,l2,l3;
            ldsm4(h0,h1,h2,h3, sb + 2*PLANE + bAddr[ntp]);
            ldsm4(l0,l1,l2,l3, sb + 3*PLANE + bAddr[ntp]);
            uint32_t bH0[2]={h0,h1}, bH1[2]={h2,h3}, bL0[2]={l0,l1}, bL1[2]={l2,l3};
            #pragma unroll
            for (int mt=0;mt<2;mt++){
                mma16816(acc[mt][2*ntp+0], afH[mt], bH0);
                mma16816(acc[mt][2*ntp+0], afL[mt], bH0);
                mma16816(acc[mt][2*ntp+0], afH[mt], bL0);
                mma16816(acc[mt][2*ntp+1], afH[mt], bH1);
                mma16816(acc[mt][2*ntp+1], afL[mt], bH1);
                mma16816(acc[mt][2*ntp+1], afH[mt], bL1);
            }
        }

        if (c + 2 < nchunk) issue(c+2);
        CP_COMMIT();
    }

    #pragma unroll
    for (int mt=0;mt<2;mt++){
        #pragma unroll
        for (int hf=0;hf<2;hf++){
            const int m = m0 + wm*32 + mt*16 + gid + hf*8;
            const size_t rb = (size_t)(b*N_SEQ) + m;
            float* Crow = Cf ? Cf + rb*ldc + coff : (float*)0;
            const float* resrow = (MODE==1) ? res + rb*256 : (const float*)0;
            #pragma unroll
            for (int nt=0;nt<8;nt++){
                const int n = n0 + wn*64 + nt*8 + tig*2;
                float v0 = acc[mt][nt][hf*2+0];
                float v1 = acc[mt][nt][hf*2+1];
                if (MODE == 0 || MODE == 1){
                    float r0=0.f, r1=0.f;
                    if (MODE == 1){
                        float2 rv = *(const float2*)(resrow + n);
                        r0 = rv.x; r1 = rv.y;
                    }
                    float sc0 = bng[n+0]*rsqrtf(bnv[n+0]+1e-5f);
                    float sc1 = bng[n+1]*rsqrtf(bnv[n+1]+1e-5f);
                    v0 = fmaxf(v0*sc0 + (bnb[n+0]-bnm[n+0]*sc0) + r0, 0.f);
                    v1 = fmaxf(v1*sc1 + (bnb[n+1]-bnm[n+1]*sc1) + r1, 0.f);
                } else if (MODE == 2){
                    v0 = fmaxf(v0 + bias[n+0], 0.f);
                    v1 = fmaxf(v1 + bias[n+1], 0.f);
                } else if (MODE == 3){
                    v0 += bias[n+0]; v1 += bias[n+1];
                }
                if (OUTHL){
                    __nv_bfloat162 h2 = __floats2bfloat162_rn(v0, v1);
                    float q0 = v0 - __bfloat162float(h2.x);
                    float q1 = v1 - __bfloat162float(h2.y);
                    __nv_bfloat162 l2 = __floats2bfloat162_rn(q0, q1);
                    *(__nv_bfloat162*)(CH + rb*ldc + coff + n) = h2;
                    *(__nv_bfloat162*)(CL + rb*ldc + coff + n) = l2;
                } else {
                    *(float2*)(Crow + n) = make_float2(v0, v1);
                }
            }
        }
    }
}

// ======================= dedicated NMP GEMM =======================
// x_nmp[i,d] = sum_j (E[i,j]*mask[i,j]) * msg[j,d]; M=128, N=256, K=2048.
// 512 threads = 16 warps (4M x 4N). A = E*mask split in staging (FMA),
// B = msgT bf16 planes via cp.async. Writes xin[:,256:512] hi/lo planes.
__global__ __launch_bounds__(512, 1) void nmp_gemm(const float* __restrict__ mask){
    extern __shared__ char sm[];
    const uint32_t smb = (uint32_t)__cvta_generic_to_shared(sm);

    const int tid  = threadIdx.x;
    const int wid  = tid >> 5;
    const int lane = tid & 31;
    const int gid  = lane >> 2;
    const int tig  = lane & 3;
    const int wm   = wid & 3;
    const int wn   = wid >> 2;

    const int m0 = blockIdx.x * 128;
    const int b  = blockIdx.y;

    const __nv_bfloat16* WHb = g_mtH + (size_t)b*256*N_SEQ;
    const __nv_bfloat16* WLb = g_mtL + (size_t)b*256*N_SEQ;
    const float* Eb = g_E  + (size_t)b*N_SEQ*N_SEQ;
    const float* Mb = mask + (size_t)b*N_SEQ*N_SEQ;

    const int rowA = tid >> 2;
    const int jq   = (tid & 3) * 4;
    const int rowB  = tid >> 1;
    const int halfB = tid & 1;

    float acc[2][8][4];
    #pragma unroll
    for (int mt=0;mt<2;mt++)
        #pragma unroll
        for (int nt=0;nt<8;nt++)
            #pragma unroll
            for (int e=0;e<4;e++) acc[mt][nt][e]=0.f;

    const int nchunk = N_SEQ / 16;

    auto issue = [&](int c){
        const uint32_t sb = smb + (c%3)*NSTAGE;
        const int kt = c*16;
        {
            const int kA = kt + jq;
            const size_t off = (size_t)(m0+rowA)*N_SEQ + kA;
            float4 e4 = *(const float4*)(Eb + off);
            float4 m4 = *(const float4*)(Mb + off);
            float v0 = e4.x*m4.x, v1 = e4.y*m4.y, v2 = e4.z*m4.z, v3 = e4.w*m4.w;
            uint32_t h0,l0,h1,l1;
            split2(v0,v1,h0,l0); split2(v2,v3,h1,l1);
            uint32_t da = sb + rowA*48 + jq*2;
            asm volatile("st.shared.v2.b32 [%0], {%1,%2};" :: "r"(da), "r"(h0), "r"(h1) : "memory");
            asm volatile("st.shared.v2.b32 [%0], {%1,%2};" :: "r"(da + PLANE), "r"(l0), "r"(l1) : "memory");
        }
        {
            const size_t wo = (size_t)rowB*N_SEQ + kt + halfB*8;
            const uint32_t db = sb + 2*PLANE + rowB*48 + halfB*16;
            cpa(db,           WHb + wo, 16);
            cpa(db + 12288,   WLb + wo, 16);
        }
    };

    const uint32_t arow = (lane & 7) + (lane & 8);
    const uint32_t aoff = ((lane >> 4) & 1) * 16;
    const uint32_t brow = (lane & 7) + ((lane & 16) ? 8 : 0);
    const uint32_t boff = ((lane >> 3) & 1) * 16;
    uint32_t aAddr[2], bAddr[4];
    #pragma unroll
    for (int mt=0;mt<2;mt++)
        aAddr[mt] = (wm*32 + mt*16 + arow)*48 + aoff;
    #pragma unroll
    for (int ntp=0;ntp<4;ntp++)
        bAddr[ntp] = 2*PLANE + (wn*64 + ntp*16 + brow)*48 + boff;

    issue(0); CP_COMMIT();
    issue(1); CP_COMMIT();

    for (int c = 0; c < nchunk; c++){
        CP_WAIT1();
        __syncthreads();
        const uint32_t sb = smb + (c%3)*NSTAGE;

        uint32_t afH[2][4], afL[2][4];
        #pragma unroll
        for (int mt=0;mt<2;mt++){
            ldsm4(afH[mt][0],afH[mt][1],afH[mt][2],afH[mt][3], sb + aAddr[mt]);
            ldsm4(afL[mt][0],afL[mt][1],afL[mt][2],afL[mt][3], sb + PLANE + aAddr[mt]);
        }
        #pragma unroll
        for (int ntp=0;ntp<4;ntp++){
            uint32_t h0,h1,h2,h3, l0,l1,l2,l3;
            ldsm4(h0,h1,h2,h3, sb + bAddr[ntp]);
            ldsm4(l0,l1,l2,l3, sb + 12288 + bAddr[ntp]);
            uint32_t bH0[2]={h0,h1}, bH1[2]={h2,h3}, bL0[2]={l0,l1}, bL1[2]={l2,l3};
            #pragma unroll
            for (int mt=0;mt<2;mt++){
                mma16816(acc[mt][2*ntp+0], afH[mt], bH0);
                mma16816(acc[mt][2*ntp+0], afL[mt], bH0);
                mma16816(acc[mt][2*ntp+0], afH[mt], bL0);
                mma16816(acc[mt][2*ntp+1], afH[mt], bH1);
                mma16816(acc[mt][2*ntp+1], afL[mt], bH1);
                mma16816(acc[mt][2*ntp+1], afH[mt], bL1);
            }
        }

        if (c + 2 < nchunk) issue(c+2);
        CP_COMMIT();
    }

    #pragma unroll
    for (int mt=0;mt<2;mt++){
        #pragma unroll
        for (int hf=0;hf<2;hf++){
            const int m = m0 + wm*32 + mt*16 + gid + hf*8;
            const size_t rb = (size_t)(b*N_SEQ) + m;
            #pragma unroll
            for (int nt=0;nt<8;nt++){
                const int n = wn*64 + nt*8 + tig*2;
                float v0 = acc[mt][nt][hf*2+0];
                float v1 = acc[mt][nt][hf*2+1];
                __nv_bfloat162 h2 = __floats2bfloat162_rn(v0, v1);
                float q0 = v0 - __bfloat162float(h2.x);
                float q1 = v1 - __bfloat162float(h2.y);
                __nv_bfloat162 l2 = __floats2bfloat162_rn(q0, q1);
                *(__nv_bfloat162*)(g_xinH + rb*512 + 256 + n) = h2;
                *(__nv_bfloat162*)(g_xinL + rb*512 + 256 + n) = l2;
            }
        }
    }
}

// ======================= launch =======================
extern "C" void kernel_launch(void* const* d_in, const int* in_sizes, int n_in,
                              void* d_out, int out_size){
    (void)in_sizes; (void)n_in; (void)out_size;
    const float* x       = (const float*)d_in[0];
    const float* mask    = (const float*)d_in[1];
    const float* w_se    = (const float*)d_in[2];
    const float* b_se    = (const float*)d_in[3];
    const float* conv1_w = (const float*)d_in[4];
    const float* bn1_g   = (const float*)d_in[5];
    const float* bn1_b   = (const float*)d_in[6];
    const float* bn1_m   = (const float*)d_in[7];
    const float* bn1_v   = (const float*)d_in[8];
    const float* conv2_w = (const float*)d_in[9];
    const float* bn2_g   = (const float*)d_in[10];
    const float* bn2_b   = (const float*)d_in[11];
    const float* bn2_m   = (const float*)d_in[12];
    const float* bn2_v   = (const float*)d_in[13];
    const float* w_msg   = (const float*)d_in[14];
    const float* b_msg   = (const float*)d_in[15];
    const float* w_ih    = (const float*)d_in[16];
    const float* b_ih    = (const float*)d_in[17];
    const float* w_hh    = (const float*)d_in[18];
    const float* b_hh    = (const float*)d_in[19];
    float* out = (float*)d_out;

    __nv_bfloat16 *xH,*xL,*h1H,*h1L,*xinH,*xinL;
    __nv_bfloat16 *w1H,*w1L,*wmH,*wmL,*whhH,*whhL,*wihH,*wihL,*w2H,*w2L;
    float *msgp,*gip,*ghp;
    cudaGetSymbolAddress((void**)&xH, g_xH);   cudaGetSymbolAddress((void**)&xL, g_xL);
    cudaGetSymbolAddress((void**)&h1H, g_h1H); cudaGetSymbolAddress((void**)&h1L, g_h1L);
    cudaGetSymbolAddress((void**)&xinH, g_xinH); cudaGetSymbolAddress((void**)&xinL, g_xinL);
    cudaGetSymbolAddress((void**)&w1H, g_w1H); cudaGetSymbolAddress((void**)&w1L, g_w1L);
    cudaGetSymbolAddress((void**)&wmH, g_wmH); cudaGetSymbolAddress((void**)&wmL, g_wmL);
    cudaGetSymbolAddress((void**)&whhH, g_whhH); cudaGetSymbolAddress((void**)&whhL, g_whhL);
    cudaGetSymbolAddress((void**)&wihH, g_wihH); cudaGetSymbolAddress((void**)&wihL, g_wihL);
    cudaGetSymbolAddress((void**)&w2H, g_w2H); cudaGetSymbolAddress((void**)&w2L, g_w2L);
    cudaGetSymbolAddress((void**)&msgp, g_msg);
    cudaGetSymbolAddress((void**)&gip, g_gi);
    cudaGetSymbolAddress((void**)&ghp, g_gh);

    cudaFuncSetAttribute(mm_gemm<0,0,false,true>,  cudaFuncAttributeMaxDynamicSharedMemorySize, SMEM_BYTES);
    cudaFuncSetAttribute(mm_gemm<0,2,false,false>, cudaFuncAttributeMaxDynamicSharedMemorySize, SMEM_BYTES);
    cudaFuncSetAttribute(mm_gemm<1,1,false,true>,  cudaFuncAttributeMaxDynamicSharedMemorySize, SMEM_BYTES);
    cudaFuncSetAttribute(mm_gemm<0,3,false,false>, cudaFuncAttributeMaxDynamicSharedMemorySize, SMEM_BYTES);
    cudaFuncSetAttribute(nmp_gemm, cudaFuncAttributeMaxDynamicSharedMemorySize, NSMEM_BYTES);

    // prep: splits + s-embedding + symmetric exp
    split_arr<<<(NTOK*D+255)/256,256>>>(x, xH, xL, NTOK*D);
    split_arr<<<(D*D+255)/256,256>>>(conv1_w, w1H, w1L, D*D);
    split_arr<<<(D*D+255)/256,256>>>(w_msg, wmH, wmL, D*D);
    split_arr<<<(3*D*D+255)/256,256>>>(w_hh, whhH, whhL, 3*D*D);
    split_arr<<<(3*D*2*D+255)/256,256>>>(w_ih, wihH, wihL, 3*D*2*D);
    repack_w2_split<<<(D*D*17+255)/256,256>>>(conv2_w);
    se_kernel<<<NTOK/8,256>>>(x, w_se, b_se);
    exp_kernel<<<dim3(N_SEQ/64, N_SEQ/64, NB),256>>>();

    dim3 g2(2,16,NB), g6(6,16,NB);
    // conv1 -> bn1+relu -> h1 planes
    mm_gemm<0,0,false,true><<<g2,256,SMEM_BYTES>>>(xH, xL, D, w1H, w1L, D,
        nullptr, h1H, h1L, D, 0, D, nullptr, bn1_g, bn1_b, bn1_m, bn1_v, nullptr);
    // msg = relu(x@w_msg^T+b) -> fp32 (for transpose)
    mm_gemm<0,2,false,false><<<g2,256,SMEM_BYTES>>>(xH, xL, D, wmH, wmL, D,
        msgp, nullptr, nullptr, D, 0, D, b_msg, nullptr,nullptr,nullptr,nullptr, nullptr);
    transpose_msg<<<dim3(N_SEQ/32, D/32, NB),256>>>();
    // conv2 (im2col over h1 planes) + bn2 + residual(x) + relu -> xin[:,0:256] planes
    mm_gemm<1,1,false,true><<<g2,256,SMEM_BYTES>>>(h1H, h1L, D, w2H, w2L, D*17,
        nullptr, xinH, xinL, 2*D, 0, D*17, nullptr, bn2_g, bn2_b, bn2_m, bn2_v, x);
    // NMP: (E*mask) @ msg -> xin[:,256:512] planes
    nmp_gemm<<<dim3(N_SEQ/128, NB),512,NSMEM_BYTES>>>(mask);
    // gh = x @ w_hh^T + b_hh (fp32)
    mm_gemm<0,3,false,false><<<g6,256,SMEM_BYTES>>>(xH, xL, D, whhH, whhL, D,
        ghp, nullptr, nullptr, 3*D, 0, D, b_hh, nullptr,nullptr,nullptr,nullptr, nullptr);
    // gi = xin @ w_ih^T + b_ih (fp32)
    mm_gemm<0,3,false,false><<<g6,256,SMEM_BYTES>>>(xinH, xinL, 2*D, wihH, wihL, 2*D,
        gip, nullptr, nullptr, 3*D, 0, 2*D, b_ih, nullptr,nullptr,nullptr,nullptr, nullptr);
    // GRU combine
    combine_kernel<<<(NTOK*64)/256,256>>>(x, out);
}